// round 4
// baseline (speedup 1.0000x reference)
#include <cuda_runtime.h>
#include <float.h>

#define NA 8400
#define NB 64
#define NC 32
#define MAXD 100
#define CONF_T 0.25f
#define IOU_T 0.45f

#define NT1 256
#define NJ (NA / 4)

#define NT2 1024
#define NW 32
#define NSLOT 9          // ceil(8400/1024); slots 0..7 always valid, slot 8 only for tid<208

// scratch (static device globals — allowed)
__device__ float4        g_box[NB * NA];
__device__ float         g_sc [NB * NA];
__device__ unsigned char g_cls[NB * NA];

// NMS smem: float4 box[NA] | float area[NA] | u8 cls[NA]
#define SM_BOX_B  (NA * 16)
#define SM_AREA_B (NA * 4)
#define SM_CLS_B  (NA)
#define SMEM2_BYTES (SM_BOX_B + SM_AREA_B + SM_CLS_B)

// ---------------- Kernel 1: decode (full-chip, streaming) ----------------
__global__ __launch_bounds__(NT1)
void decode_kernel(const float* __restrict__ in)
{
    const int j = blockIdx.x * NT1 + threadIdx.x;
    const int b = blockIdx.y;
    if (j >= NJ) return;
    const float* base = in + (size_t)b * (4 + NC) * NA;

    const float4 xc = ((const float4*)(base + 0 * NA))[j];
    const float4 yc = ((const float4*)(base + 1 * NA))[j];
    const float4 ww = ((const float4*)(base + 2 * NA))[j];
    const float4 hh = ((const float4*)(base + 3 * NA))[j];

    float4 best = make_float4(-FLT_MAX, -FLT_MAX, -FLT_MAX, -FLT_MAX);
    int4   cls  = make_int4(0, 0, 0, 0);
    #pragma unroll
    for (int k = 0; k < NC; ++k) {
        float4 v = ((const float4*)(base + (4 + k) * NA))[j];
        if (v.x > best.x) { best.x = v.x; cls.x = k; }
        if (v.y > best.y) { best.y = v.y; cls.y = k; }
        if (v.z > best.z) { best.z = v.z; cls.z = k; }
        if (v.w > best.w) { best.w = v.w; cls.w = k; }
    }

    const int a0 = 4 * j;
    float4* ob = g_box + (size_t)b * NA + a0;
    float h2, w2;
    h2 = hh.x * 0.5f; w2 = ww.x * 0.5f;
    ob[0] = make_float4(fminf(fmaxf(yc.x - h2, 0.f), 1.f), fminf(fmaxf(xc.x - w2, 0.f), 1.f),
                        fminf(fmaxf(yc.x + h2, 0.f), 1.f), fminf(fmaxf(xc.x + w2, 0.f), 1.f));
    h2 = hh.y * 0.5f; w2 = ww.y * 0.5f;
    ob[1] = make_float4(fminf(fmaxf(yc.y - h2, 0.f), 1.f), fminf(fmaxf(xc.y - w2, 0.f), 1.f),
                        fminf(fmaxf(yc.y + h2, 0.f), 1.f), fminf(fmaxf(xc.y + w2, 0.f), 1.f));
    h2 = hh.z * 0.5f; w2 = ww.z * 0.5f;
    ob[2] = make_float4(fminf(fmaxf(yc.z - h2, 0.f), 1.f), fminf(fmaxf(xc.z - w2, 0.f), 1.f),
                        fminf(fmaxf(yc.z + h2, 0.f), 1.f), fminf(fmaxf(xc.z + w2, 0.f), 1.f));
    h2 = hh.w * 0.5f; w2 = ww.w * 0.5f;
    ob[3] = make_float4(fminf(fmaxf(yc.w - h2, 0.f), 1.f), fminf(fmaxf(xc.w - w2, 0.f), 1.f),
                        fminf(fmaxf(yc.w + h2, 0.f), 1.f), fminf(fmaxf(xc.w + w2, 0.f), 1.f));

    float4 sc;
    sc.x = (best.x >= CONF_T) ? best.x : -1.0f;
    sc.y = (best.y >= CONF_T) ? best.y : -1.0f;
    sc.z = (best.z >= CONF_T) ? best.z : -1.0f;
    sc.w = (best.w >= CONF_T) ? best.w : -1.0f;
    *(float4*)(g_sc + (size_t)b * NA + a0) = sc;
    *(uchar4*)(g_cls + (size_t)b * NA + a0) =
        make_uchar4((unsigned char)cls.x, (unsigned char)cls.y,
                    (unsigned char)cls.z, (unsigned char)cls.w);
}

// ---------------- Kernel 2: NMS — scores register-resident ----------------
__global__ __launch_bounds__(NT2, 1)
void nms_kernel(float* __restrict__ out)
{
    extern __shared__ unsigned char smem_raw[];
    float4*        s_box  = (float4*)smem_raw;
    float*         s_area = (float*)(smem_raw + SM_BOX_B);
    unsigned char* s_cls  = (unsigned char*)(smem_raw + SM_BOX_B + SM_AREA_B);

    __shared__ float rv[2][NW];
    __shared__ int   ri[2][NW];

    const int b    = blockIdx.x;
    const int tid  = threadIdx.x;
    const int lane = tid & 31;
    const int w    = tid >> 5;

    float* out_boxes = out;                          // [NB, MAXD, 4]
    float* out_cls   = out + (size_t)NB * MAXD * 4;  // [NB, MAXD]
    float* out_scr   = out_cls + (size_t)NB * MAXD;  // [NB, MAXD]
    float* out_num   = out_scr + (size_t)NB * MAXD;  // [NB]

    float sc[NSLOT];
    float bv = -FLT_MAX;
    int   bi = 0x7fffffff;

    // ---- load scratch -> smem, scores -> registers, seed argmax ----
    const size_t off = (size_t)b * NA;
    #pragma unroll
    for (int k = 0; k < NSLOT; ++k) {
        const int a = tid + (k << 10);
        if (a < NA) {
            float4 f4 = g_box[off + a];
            s_box[a]  = f4;
            s_area[a] = (f4.z - f4.x) * (f4.w - f4.y);
            s_cls[a]  = g_cls[off + a];
            float s   = g_sc[off + a];
            sc[k]     = s;
            if (s > bv) { bv = s; bi = a; }   // slots ascend in idx => thread-local first-max
        } else {
            sc[k] = -1.0f;
        }
    }
    __syncthreads();

    for (int it = 0; ; ++it) {
        const int par = it & 1;
        // warp butterfly argmax with min-index tie-break
        #pragma unroll
        for (int offd = 16; offd > 0; offd >>= 1) {
            float ov = __shfl_xor_sync(0xffffffffu, bv, offd);
            int   oi = __shfl_xor_sync(0xffffffffu, bi, offd);
            if (ov > bv || (ov == bv && oi < bi)) { bv = ov; bi = oi; }
        }
        if (lane == 0) { rv[par][w] = bv; ri[par][w] = bi; }
        __syncthreads();   // only barrier per iteration
        float pv = rv[par][lane];
        int   pi = ri[par][lane];
        #pragma unroll
        for (int offd = 16; offd > 0; offd >>= 1) {
            float ov = __shfl_xor_sync(0xffffffffu, pv, offd);
            int   oi = __shfl_xor_sync(0xffffffffu, pi, offd);
            if (ov > pv || (ov == pv && oi < pi)) { pv = ov; pi = oi; }
        }

        if (pv <= 0.0f) {   // live set empty: remaining slots exact zeros
            for (int i = it * 4 + tid; i < MAXD * 4; i += NT2)
                out_boxes[(size_t)b * MAXD * 4 + i] = 0.0f;
            for (int i = it + tid; i < MAXD; i += NT2) {
                out_cls[(size_t)b * MAXD + i] = 0.0f;
                out_scr[(size_t)b * MAXD + i] = 0.0f;
            }
            if (tid == 0) out_num[b] = (float)it;
            return;
        }

        const float4 pb     = s_box[pi];    // uniform LDS broadcast
        const float  area_a = s_area[pi];
        if (tid == 0) {
            float* ob = out_boxes + ((size_t)b * MAXD + it) * 4;
            ob[0] = pb.x; ob[1] = pb.y; ob[2] = pb.z; ob[3] = pb.w;
            out_cls[(size_t)b * MAXD + it] = (float)s_cls[pi];
            out_scr[(size_t)b * MAXD + it] = pv;
        }
        if (it == MAXD - 1) {
            if (tid == 0) out_num[b] = (float)MAXD;
            return;
        }

        // fused suppress + next-argmax over register-resident scores
        bv = -FLT_MAX; bi = 0x7fffffff;

#define SLOT_BODY(AREAL, ALOAD, S)                                          \
        {                                                                   \
            float4 bb = s_box[ALOAD];                                       \
            float  ab = s_area[ALOAD];                                      \
            float y1 = fmaxf(pb.x, bb.x);                                   \
            float x1 = fmaxf(pb.y, bb.y);                                   \
            float y2 = fminf(pb.z, bb.z);                                   \
            float x2 = fminf(pb.w, bb.w);                                   \
            float inter = fmaxf(y2 - y1, 0.0f) * fmaxf(x2 - x1, 0.0f);      \
            float uni   = area_a + ab - inter;                              \
            float iou   = (uni > 0.0f) ? (inter / uni) : 0.0f;              \
            bool kill = (iou > IOU_T) || ((AREAL) == pi);                   \
            S = kill ? -1.0f : S;                                           \
            if (S > bv) { bv = S; bi = (AREAL); }                           \
        }

        #pragma unroll
        for (int k = 0; k < NSLOT - 1; ++k) {
            const int a = tid + (k << 10);   // < 8192 < NA, always valid
            SLOT_BODY(a, a, sc[k]);
        }
        {
            const int a  = tid + ((NSLOT - 1) << 10);
            const int ac = (a < NA) ? a : 0;   // clamp load addr; sc[8] is -1 when invalid
            SLOT_BODY(a, ac, sc[NSLOT - 1]);
        }
#undef SLOT_BODY
        // no extra barrier: rv/ri parity-double-buffered; s_box/s_area read-only
    }
}

extern "C" void kernel_launch(void* const* d_in, const int* in_sizes, int n_in,
                              void* d_out, int out_size)
{
    (void)in_sizes; (void)n_in; (void)out_size;
    const float* in = (const float*)d_in[0];
    float* out = (float*)d_out;

    dim3 g1((NJ + NT1 - 1) / NT1, NB);
    decode_kernel<<<g1, NT1>>>(in);

    cudaFuncSetAttribute(nms_kernel,
                         cudaFuncAttributeMaxDynamicSharedMemorySize,
                         (int)SMEM2_BYTES);
    nms_kernel<<<NB, NT2, SMEM2_BYTES>>>(out);
}

// round 5
// speedup vs baseline: 2.5698x; 2.5698x over previous
#include <cuda_runtime.h>
#include <float.h>

#define NA 8400
#define NB 64
#define NC 32
#define MAXD 100
#define CONF_T 0.25f
#define IOU_T 0.45f

#define NT1 256
#define NJ (NA / 4)

#define NT2 1024
#define NSLOT 9
#define CAP 512
#define INT_MINV ((int)0x80000000)

__device__ float4        g_box[NB * NA];
__device__ float         g_sc [NB * NA];
__device__ unsigned char g_cls[NB * NA];

// dynamic smem offsets (nms kernel)
#define OFF_AREA (NA * 16)                 // after float4 box[NA]
#define OFF_CLS  (OFF_AREA + NA * 4)
#define OFF_K64  (OFF_CLS + NA)            // 176400, 8-aligned
#define OFF_ACCB (OFF_K64 + CAP * 8)       // 180496, 16-aligned
#define OFF_ACCA (OFF_ACCB + MAXD * 16)
#define SMEM2_BYTES (OFF_ACCA + MAXD * 4)  // 182496

// ---------------- Kernel 1: decode (unchanged, ~12us) ----------------
__global__ __launch_bounds__(NT1)
void decode_kernel(const float* __restrict__ in)
{
    const int j = blockIdx.x * NT1 + threadIdx.x;
    const int b = blockIdx.y;
    if (j >= NJ) return;
    const float* base = in + (size_t)b * (4 + NC) * NA;

    const float4 xc = ((const float4*)(base + 0 * NA))[j];
    const float4 yc = ((const float4*)(base + 1 * NA))[j];
    const float4 ww = ((const float4*)(base + 2 * NA))[j];
    const float4 hh = ((const float4*)(base + 3 * NA))[j];

    float4 best = make_float4(-FLT_MAX, -FLT_MAX, -FLT_MAX, -FLT_MAX);
    int4   cls  = make_int4(0, 0, 0, 0);
    #pragma unroll
    for (int k = 0; k < NC; ++k) {
        float4 v = ((const float4*)(base + (4 + k) * NA))[j];
        if (v.x > best.x) { best.x = v.x; cls.x = k; }
        if (v.y > best.y) { best.y = v.y; cls.y = k; }
        if (v.z > best.z) { best.z = v.z; cls.z = k; }
        if (v.w > best.w) { best.w = v.w; cls.w = k; }
    }

    const int a0 = 4 * j;
    float4* ob = g_box + (size_t)b * NA + a0;
    float h2, w2;
    h2 = hh.x * 0.5f; w2 = ww.x * 0.5f;
    ob[0] = make_float4(fminf(fmaxf(yc.x - h2, 0.f), 1.f), fminf(fmaxf(xc.x - w2, 0.f), 1.f),
                        fminf(fmaxf(yc.x + h2, 0.f), 1.f), fminf(fmaxf(xc.x + w2, 0.f), 1.f));
    h2 = hh.y * 0.5f; w2 = ww.y * 0.5f;
    ob[1] = make_float4(fminf(fmaxf(yc.y - h2, 0.f), 1.f), fminf(fmaxf(xc.y - w2, 0.f), 1.f),
                        fminf(fmaxf(yc.y + h2, 0.f), 1.f), fminf(fmaxf(xc.y + w2, 0.f), 1.f));
    h2 = hh.z * 0.5f; w2 = ww.z * 0.5f;
    ob[2] = make_float4(fminf(fmaxf(yc.z - h2, 0.f), 1.f), fminf(fmaxf(xc.z - w2, 0.f), 1.f),
                        fminf(fmaxf(yc.z + h2, 0.f), 1.f), fminf(fmaxf(xc.z + w2, 0.f), 1.f));
    h2 = hh.w * 0.5f; w2 = ww.w * 0.5f;
    ob[3] = make_float4(fminf(fmaxf(yc.w - h2, 0.f), 1.f), fminf(fmaxf(xc.w - w2, 0.f), 1.f),
                        fminf(fmaxf(yc.w + h2, 0.f), 1.f), fminf(fmaxf(xc.w + w2, 0.f), 1.f));

    float4 sc;
    sc.x = (best.x >= CONF_T) ? best.x : -1.0f;
    sc.y = (best.y >= CONF_T) ? best.y : -1.0f;
    sc.z = (best.z >= CONF_T) ? best.z : -1.0f;
    sc.w = (best.w >= CONF_T) ? best.w : -1.0f;
    *(float4*)(g_sc + (size_t)b * NA + a0) = sc;
    *(uchar4*)(g_cls + (size_t)b * NA + a0) =
        make_uchar4((unsigned char)cls.x, (unsigned char)cls.y,
                    (unsigned char)cls.z, (unsigned char)cls.w);
}

// ---------------- Kernel 2: sorted-scan NMS ----------------
__global__ __launch_bounds__(NT2, 1)
void nms_kernel(float* __restrict__ out)
{
    extern __shared__ unsigned char sm[];
    float4*             s_box  = (float4*)sm;
    float*              s_area = (float*)(sm + OFF_AREA);
    unsigned char*      s_cls  = sm + OFF_CLS;
    unsigned long long* s_k    = (unsigned long long*)(sm + OFF_K64);
    float4*             s_accb = (float4*)(sm + OFF_ACCB);
    float*              s_acca = (float*)(sm + OFF_ACCA);

    __shared__ int cnt_w[32];
    __shared__ int s_tot;
    __shared__ int s_gc;

    const int b    = blockIdx.x;
    const int tid  = threadIdx.x;
    const int lane = tid & 31;
    const int w    = tid >> 5;

    float* out_boxes = out;                          // [NB, MAXD, 4]
    float* out_cls   = out + (size_t)NB * MAXD * 4;  // [NB, MAXD]
    float* out_scr   = out_cls + (size_t)NB * MAXD;  // [NB, MAXD]
    float* out_num   = out_scr + (size_t)NB * MAXD;  // [NB]

#define ZERO_FILL_RETURN(ACC)                                              \
    do {                                                                   \
        for (int i = (ACC) * 4 + tid; i < MAXD * 4; i += NT2)              \
            out_boxes[(size_t)b * MAXD * 4 + i] = 0.0f;                    \
        for (int i = (ACC) + tid; i < MAXD; i += NT2) {                    \
            out_cls[(size_t)b * MAXD + i] = 0.0f;                          \
            out_scr[(size_t)b * MAXD + i] = 0.0f;                          \
        }                                                                  \
        if (tid == 0) out_num[b] = (float)(ACC);                           \
        return;                                                            \
    } while (0)

    // ---- load: boxes/areas/cls -> smem, score keys -> registers ----
    int key[NSLOT];
    const size_t off = (size_t)b * NA;
    #pragma unroll
    for (int k = 0; k < NSLOT; ++k) {
        const int a = tid + (k << 10);
        if (a < NA) {
            float4 f4 = g_box[off + a];
            s_box[a]  = f4;
            s_area[a] = (f4.z - f4.x) * (f4.w - f4.y);
            s_cls[a]  = g_cls[off + a];
            key[k]    = __float_as_int(g_sc[off + a]);   // signed-int order ok for {-1}∪[0.25,1)
        } else {
            key[k] = __float_as_int(-1.0f);   // sorts into the <=0 tail; never dereferenced
        }
    }
    __syncthreads();

    int acc   = 0;
    int Uprev = 0x7FFFFFFF;   // tranche = keys in [ustar, Uprev)

    for (;;) {
        // ---- binary search: smallest ustar with count([ustar,Uprev)) <= CAP ----
        int lo = INT_MINV, hi = Uprev;
        while (lo < hi) {
            const int mid = (int)(((long long)lo + (long long)hi) >> 1);
            int c = 0;
            #pragma unroll
            for (int k = 0; k < NSLOT; ++k)
                c += (key[k] >= mid && key[k] < Uprev) ? 1 : 0;
            #pragma unroll
            for (int o = 16; o > 0; o >>= 1) c += __shfl_xor_sync(0xffffffffu, c, o);
            if (lane == 0) cnt_w[w] = c;
            __syncthreads();
            if (tid < 32) {
                int t = cnt_w[tid];
                #pragma unroll
                for (int o = 16; o > 0; o >>= 1) t += __shfl_xor_sync(0xffffffffu, t, o);
                if (tid == 0) s_tot = t;
            }
            __syncthreads();
            const int cnt = s_tot;
            if (cnt <= CAP) hi = mid; else lo = mid + 1;
        }
        int ustar = lo;

        // ---- gather tranche (retry once at INT_MIN for the degenerate tie case) ----
        int g = 0;
        for (int attempt = 0; attempt < 2; ++attempt) {
            if (tid == 0) s_gc = 0;
            __syncthreads();
            #pragma unroll
            for (int k = 0; k < NSLOT; ++k) {
                if (key[k] >= ustar && key[k] < Uprev) {
                    int pos = atomicAdd(&s_gc, 1);
                    if (pos < CAP) {
                        const int a = tid + (k << 10);
                        const unsigned u = (unsigned)key[k] ^ 0x80000000u;
                        s_k[pos] = ((unsigned long long)(~u) << 32) | (unsigned)a;
                    }
                }
            }
            __syncthreads();
            g = s_gc; if (g > CAP) g = CAP;
            __syncthreads();
            if (g > 0 || ustar == INT_MINV) break;
            ustar = INT_MINV;
        }
        if (g == 0) ZERO_FILL_RETURN(acc);   // nothing remains anywhere

        // pad + ascending bitonic sort (asc key64 = desc score, asc idx)
        for (int i = g + tid; i < CAP; i += NT2) s_k[i] = 0xFFFFFFFFFFFFFFFFull;
        __syncthreads();
        for (int kk = 2; kk <= CAP; kk <<= 1) {
            for (int j = kk >> 1; j > 0; j >>= 1) {
                const int i = tid;
                if (i < CAP) {
                    const int ixj = i ^ j;
                    if (ixj > i) {
                        unsigned long long A = s_k[i], B = s_k[ixj];
                        const bool up = ((i & kk) == 0);
                        if ((A > B) == up) { s_k[i] = B; s_k[ixj] = A; }
                    }
                }
                __syncthreads();
            }
        }

        // ---- sequential scan: candidate vs accepted set ----
        for (int p = 0; p < g; ++p) {
            const unsigned long long kk = s_k[p];
            const int idx = (int)(unsigned)(kk & 0xFFFFFFFFull);
            const unsigned um = ~(unsigned)(kk >> 32);
            const float s = __int_as_float((int)(um ^ 0x80000000u));
            if (!(s > 0.0f)) ZERO_FILL_RETURN(acc);   // all further anchors are <= 0

            const float4 cb = s_box[idx];
            const float  ca = s_area[idx];
            int pred = 0;
            if (tid < acc) {
                const float4 a4 = s_accb[tid];
                const float  aa = s_acca[tid];
                float y1 = fmaxf(a4.x, cb.x);
                float x1 = fmaxf(a4.y, cb.y);
                float y2 = fminf(a4.z, cb.z);
                float x2 = fminf(a4.w, cb.w);
                float inter = fmaxf(y2 - y1, 0.0f) * fmaxf(x2 - x1, 0.0f);
                float uni   = aa + ca - inter;              // area_a(accepted) + area_b - inter
                float iou   = (uni > 0.0f) ? (inter / uni) : 0.0f;
                pred = (iou > IOU_T) ? 1 : 0;
            }
            const int dead = __syncthreads_or(pred);
            if (!dead) {
                if (tid == 0) {
                    s_accb[acc] = cb;
                    s_acca[acc] = ca;
                    float* ob = out_boxes + ((size_t)b * MAXD + acc) * 4;
                    ob[0] = cb.x; ob[1] = cb.y; ob[2] = cb.z; ob[3] = cb.w;
                    out_cls[(size_t)b * MAXD + acc] = (float)s_cls[idx];
                    out_scr[(size_t)b * MAXD + acc] = s;
                }
                ++acc;
                if (acc == MAXD) {
                    if (tid == 0) out_num[b] = (float)MAXD;
                    return;
                }
                __syncthreads();   // make s_accb[acc-1] visible before next check
            }
        }

        Uprev = ustar;
        if (Uprev == INT_MINV) ZERO_FILL_RETURN(acc);   // everything was examined
    }
#undef ZERO_FILL_RETURN
}

extern "C" void kernel_launch(void* const* d_in, const int* in_sizes, int n_in,
                              void* d_out, int out_size)
{
    (void)in_sizes; (void)n_in; (void)out_size;
    const float* in = (const float*)d_in[0];
    float* out = (float*)d_out;

    dim3 g1((NJ + NT1 - 1) / NT1, NB);
    decode_kernel<<<g1, NT1>>>(in);

    cudaFuncSetAttribute(nms_kernel,
                         cudaFuncAttributeMaxDynamicSharedMemorySize,
                         (int)SMEM2_BYTES);
    nms_kernel<<<NB, NT2, SMEM2_BYTES>>>(out);
}